// round 14
// baseline (speedup 1.0000x reference)
#include <cuda_runtime.h>
#include <cuda.h>
#include <cuda_fp16.h>
#include <cstdint>
#include <cstddef>

#define NN 50000
#define EE 800000
#define EN 850000   // EE + NN (self loops)
#define GG 512
#define NBLK 196    // ceil(NN/256)
#define GTB  391    // ceil(NN/128) node tiles for tensor GEMM

// ---------------- scratch (static device globals; no allocation) ----------------
__device__ __align__(16) float    g_h  [NN * 64];
__device__ __align__(16) uint32_t g_xlh[NN * 64];   // xl as half2-packed [N][128]
__device__ __align__(16) float    g_xr [NN * 128];
__device__ __align__(16) float    g_ro [NN * 128];  // readout scratch
__device__ int   g_deg[NN];
__device__ int   g_rowoff[NN + 1];
__device__ int   g_cursor[NN];
__device__ int   g_csrsrc[EN];
__device__ int   g_bsum[256];

// ---------------- helpers ----------------
__device__ __forceinline__ uint32_t smem_to_u32(const void* smem_ptr) {
    uint32_t addr;
    asm("{ .reg .u64 tmp; cvta.to.shared.u64 tmp, %1; cvt.u32.u64 %0, tmp; }"
        : "=r"(addr) : "l"(smem_ptr));
    return addr;
}

#define SMEM_SWIZZLE_128B(byte_offset) \
    ((byte_offset) ^ (((byte_offset) >> 3) & 0x70))

// pack two floats to bf16x2 (first arg -> LOW half = lower index)
__device__ __forceinline__ uint32_t bf2(float lo, float hi) {
    uint32_t r;
    asm("cvt.rn.bf16x2.f32 %0, %1, %2;" : "=r"(r) : "f"(hi), "f"(lo));
    return r;
}
__device__ __forceinline__ float bflo(uint32_t p) { return __uint_as_float(p << 16); }
__device__ __forceinline__ float bfhi(uint32_t p) { return __uint_as_float(p & 0xffff0000u); }

__device__ __forceinline__ void ldm_x4(uint32_t* r, uint32_t addr) {
    asm volatile("ldmatrix.sync.aligned.m8n8.x4.shared.b16 {%0,%1,%2,%3}, [%4];"
        : "=r"(r[0]), "=r"(r[1]), "=r"(r[2]), "=r"(r[3]) : "r"(addr));
}
__device__ __forceinline__ void ldm_x2(uint32_t* r, uint32_t addr) {
    asm volatile("ldmatrix.sync.aligned.m8n8.x2.shared.b16 {%0,%1}, [%2];"
        : "=r"(r[0]), "=r"(r[1]) : "r"(addr));
}
__device__ __forceinline__ void mma_bf16(float* d, const uint32_t* a, const uint32_t* b) {
    asm volatile(
        "mma.sync.aligned.m16n8k16.row.col.f32.bf16.bf16.f32 "
        "{%0,%1,%2,%3}, {%4,%5,%6,%7}, {%8,%9}, {%0,%1,%2,%3};"
        : "+f"(d[0]), "+f"(d[1]), "+f"(d[2]), "+f"(d[3])
        : "r"(a[0]), "r"(a[1]), "r"(a[2]), "r"(a[3]), "r"(b[0]), "r"(b[1]));
}

__device__ __forceinline__ void split2(float x, float y, uint32_t& hp, uint32_t& lp) {
    hp = bf2(x, y);
    lp = bf2(x - bflo(hp), y - bfhi(hp));
}

// ---------------- embedding gather (+ deg init fused) ----------------
__global__ void embed_k(const int* __restrict__ x, const float* __restrict__ embed) {
    int t = blockIdx.x * blockDim.x + threadIdx.x;
    if (t >= NN * 16) return;
    int n = t >> 4, q = t & 15;
    if (q == 0) g_deg[n] = 1;
    int row = x[n];
    float4 v = *(const float4*)(embed + row * 64 + q * 4);
    *(float4*)(g_h + n * 64 + q * 4) = v;
}

// ---------------- CSR build ----------------
__global__ void hist_k(const int* __restrict__ ei) {
    int e = blockIdx.x * blockDim.x + threadIdx.x;
    if (e >= EE) return;
    atomicAdd(&g_deg[ei[EE + e]], 1);
}

__global__ void blocksum_k() {
    __shared__ int sh[8];
    int i = blockIdx.x * 256 + threadIdx.x;
    int v = (i < NN) ? g_deg[i] : 0;
#pragma unroll
    for (int o = 16; o; o >>= 1) v += __shfl_down_sync(0xffffffffu, v, o);
    if ((threadIdx.x & 31) == 0) sh[threadIdx.x >> 5] = v;
    __syncthreads();
    if (threadIdx.x == 0) {
        int s = 0;
#pragma unroll
        for (int w = 0; w < 8; w++) s += sh[w];
        g_bsum[blockIdx.x] = s;
    }
}

__global__ void bscan_k() {
    __shared__ int sh[256];
    int t = threadIdx.x;
    int v = (t < NBLK) ? g_bsum[t] : 0;
    sh[t] = v;
    __syncthreads();
#pragma unroll
    for (int off = 1; off < 256; off <<= 1) {
        int add = (t >= off) ? sh[t - off] : 0;
        __syncthreads();
        sh[t] += add;
        __syncthreads();
    }
    if (t < NBLK) g_bsum[t] = (t == 0) ? 0 : sh[t - 1];
    if (t == 0) g_rowoff[NN] = EN;
}

__global__ void scatter_scan_k() {
    __shared__ int sh[256];
    int t = threadIdx.x;
    int i = blockIdx.x * 256 + t;
    int v = (i < NN) ? g_deg[i] : 0;
    sh[t] = v;
    __syncthreads();
#pragma unroll
    for (int off = 1; off < 256; off <<= 1) {
        int add = (t >= off) ? sh[t - off] : 0;
        __syncthreads();
        sh[t] += add;
        __syncthreads();
    }
    int excl = ((t == 0) ? 0 : sh[t - 1]) + g_bsum[blockIdx.x];
    if (i < NN) { g_rowoff[i] = excl; g_cursor[i] = excl; }
}

__global__ void fill_k(const int* __restrict__ ei) {
    int t = blockIdx.x * blockDim.x + threadIdx.x;
    if (t >= EN) return;
    int s, d;
    if (t < EE) { s = ei[t]; d = ei[EE + t]; }
    else        { s = t - EE; d = s; }
    int pos = atomicAdd(&g_cursor[d], 1);
    g_csrsrc[pos] = s;
}

// ---------------- fused layer kernel: lin -> (xl half, xr fp32) ----------------
__global__ void __launch_bounds__(512) fused_layer_k(
    const float* __restrict__ h, const float* __restrict__ linW,
    const float* __restrict__ lin_b, const float* __restrict__ Wl,
    const float* __restrict__ bl, const float* __restrict__ Wr,
    const float* __restrict__ br,
    uint32_t* __restrict__ xlh, float* __restrict__ xr) {
    extern __shared__ __align__(1024) char smem[];
    const int A_H  = 0,       A_L  = 16384;    // h tile      128x64 bf16
    const int LW_H = 32768,   LW_L = 40960;    // linW        64x64  bf16 (Bt layout)
    const int A2_H = 49152,   A2_L = 65536;    // lin result  128x64 bf16
    const int BL_H = 81920,   BL_L = 98304;    // Wl          128x64 bf16 (Bt layout)
    const int BR_H = 114688,  BR_L = 131072;   // Wr

    uint32_t sb = smem_to_u32(smem);
    int tid  = threadIdx.x;                    // 0..511
    int wid  = tid >> 5;                       // 0..15
    int lane = tid & 31;
    int n0   = blockIdx.x * 128;

    // ---- stage A = h hi/lo ----
    {
        int n  = tid & 127;
        int q4 = tid >> 7;                     // 0..3
        bool valid = (n0 + n) < NN;
        const float4* ar = (const float4*)(h + (size_t)(n0 + n) * 64);
        uint32_t rowoff = (uint32_t)n * 128;
#pragma unroll
        for (int q = q4 * 4; q < q4 * 4 + 4; q += 2) {
            float4 f0 = valid ? __ldg(ar + q)     : make_float4(0.f, 0.f, 0.f, 0.f);
            float4 f1 = valid ? __ldg(ar + q + 1) : make_float4(0.f, 0.f, 0.f, 0.f);
            uint32_t h0, l0, h1, l1, h2, l2, h3, l3;
            split2(f0.x, f0.y, h0, l0);
            split2(f0.z, f0.w, h1, l1);
            split2(f1.x, f1.y, h2, l2);
            split2(f1.z, f1.w, h3, l3);
            uint32_t off = SMEM_SWIZZLE_128B(rowoff + (uint32_t)q * 8);
            *(uint4*)(smem + A_H + off) = make_uint4(h0, h1, h2, h3);
            *(uint4*)(smem + A_L + off) = make_uint4(l0, l1, l2, l3);
        }
    }
    // ---- stage linW hi/lo ----
#pragma unroll
    for (int pf = tid; pf < 32 * 64; pf += 512) {
        int j2 = pf >> 6, c = pf & 63;
        float w0 = __ldg(linW + (size_t)(2 * j2)     * 64 + c);
        float w1 = __ldg(linW + (size_t)(2 * j2 + 1) * 64 + c);
        uint32_t hp, lp;
        split2(w0, w1, hp, lp);
        uint32_t off = SMEM_SWIZZLE_128B((uint32_t)c * 128 + (uint32_t)j2 * 4);
        *(uint32_t*)(smem + LW_H + off) = hp;
        *(uint32_t*)(smem + LW_L + off) = lp;
    }
    // ---- stage Wl, Wr hi/lo ----
#pragma unroll
    for (int pf = tid; pf < 32 * 128; pf += 512) {
        int j2 = pf >> 7, c = pf & 127;
        uint32_t off = SMEM_SWIZZLE_128B((uint32_t)c * 128 + (uint32_t)j2 * 4);
        float w0 = __ldg(Wl + (size_t)(2 * j2)     * 128 + c);
        float w1 = __ldg(Wl + (size_t)(2 * j2 + 1) * 128 + c);
        uint32_t hp, lp;
        split2(w0, w1, hp, lp);
        *(uint32_t*)(smem + BL_H + off) = hp;
        *(uint32_t*)(smem + BL_L + off) = lp;
        w0 = __ldg(Wr + (size_t)(2 * j2)     * 128 + c);
        w1 = __ldg(Wr + (size_t)(2 * j2 + 1) * 128 + c);
        split2(w0, w1, hp, lp);
        *(uint32_t*)(smem + BR_H + off) = hp;
        *(uint32_t*)(smem + BR_L + off) = lp;
    }
    __syncthreads();

    uint32_t a_sel   = (uint32_t)(lane >> 4);
    uint32_t b_row_l = (uint32_t)(lane & 7);
    uint32_t b_sel   = (uint32_t)((lane >> 3) & 1);

    // ---- phase 1: lin tile ----
    {
        int rg = (wid & 7) * 16;
        int ch = wid >> 3;
        float acc[4][4];
#pragma unroll
        for (int t = 0; t < 4; t++) {
            acc[t][0] = 0.f; acc[t][1] = 0.f; acc[t][2] = 0.f; acc[t][3] = 0.f;
        }
        uint32_t a_row = (uint32_t)(rg + (lane & 15));
#pragma unroll
        for (int ks = 0; ks < 4; ks++) {
            uint32_t ah[4], al[4];
            uint32_t aoff = SMEM_SWIZZLE_128B(a_row * 128 + (uint32_t)(ks * 2 + a_sel) * 16);
            ldm_x4(ah, sb + A_H + aoff);
            ldm_x4(al, sb + A_L + aoff);
#pragma unroll
            for (int t = 0; t < 4; t++) {
                uint32_t bh[2], blo[2];
                uint32_t boff = SMEM_SWIZZLE_128B(((uint32_t)(ch * 32 + t * 8) + b_row_l) * 128 +
                                                  (uint32_t)(ks * 2 + b_sel) * 16);
                ldm_x2(bh,  sb + LW_H + boff);
                ldm_x2(blo, sb + LW_L + boff);
                mma_bf16(acc[t], ah, bh);
                mma_bf16(acc[t], ah, blo);
                mma_bf16(acc[t], al, bh);
            }
        }
        int r0 = rg + (lane >> 2);
        int r1 = r0 + 8;
#pragma unroll
        for (int t = 0; t < 4; t++) {
            int c = ch * 32 + t * 8 + 2 * (lane & 3);
            float2 bb = *(const float2*)(lin_b + c);
            float o0x = fmaxf(acc[t][0] + bb.x, 0.f);
            float o0y = fmaxf(acc[t][1] + bb.y, 0.f);
            float o1x = fmaxf(acc[t][2] + bb.x, 0.f);
            float o1y = fmaxf(acc[t][3] + bb.y, 0.f);
            uint32_t hp, lp;
            split2(o0x, o0y, hp, lp);
            uint32_t off0 = SMEM_SWIZZLE_128B((uint32_t)r0 * 128 + (uint32_t)c * 2);
            *(uint32_t*)(smem + A2_H + off0) = hp;
            *(uint32_t*)(smem + A2_L + off0) = lp;
            split2(o1x, o1y, hp, lp);
            uint32_t off1 = SMEM_SWIZZLE_128B((uint32_t)r1 * 128 + (uint32_t)c * 2);
            *(uint32_t*)(smem + A2_H + off1) = hp;
            *(uint32_t*)(smem + A2_L + off1) = lp;
        }
    }
    __syncthreads();

    // ---- phase 2: warps 0-7 -> xl (half2 packed); warps 8-15 -> xr (fp32) ----
    {
        int side = wid >> 3;
        int rg   = (wid & 7) * 16;
        const int B_H = side ? BR_H : BL_H;
        const int B_L = side ? BR_L : BL_L;
        const float* bias = side ? br : bl;

        float acc[16][4];
#pragma unroll
        for (int t = 0; t < 16; t++) {
            acc[t][0] = 0.f; acc[t][1] = 0.f; acc[t][2] = 0.f; acc[t][3] = 0.f;
        }
        uint32_t a_row = (uint32_t)(rg + (lane & 15));
#pragma unroll
        for (int ks = 0; ks < 4; ks++) {
            uint32_t ah[4], al[4];
            uint32_t aoff = SMEM_SWIZZLE_128B(a_row * 128 + (uint32_t)(ks * 2 + a_sel) * 16);
            ldm_x4(ah, sb + A2_H + aoff);
            ldm_x4(al, sb + A2_L + aoff);
#pragma unroll
            for (int t = 0; t < 16; t++) {
                uint32_t bh[2], blo[2];
                uint32_t boff = SMEM_SWIZZLE_128B(((uint32_t)(t * 8) + b_row_l) * 128 +
                                                  (uint32_t)(ks * 2 + b_sel) * 16);
                ldm_x2(bh,  sb + B_H + boff);
                ldm_x2(blo, sb + B_L + boff);
                mma_bf16(acc[t], ah, bh);
                mma_bf16(acc[t], ah, blo);
                mma_bf16(acc[t], al, bh);
            }
        }
        int r0 = n0 + rg + (lane >> 2);
        int r1 = r0 + 8;
#pragma unroll
        for (int t = 0; t < 16; t++) {
            int c = t * 8 + 2 * (lane & 3);
            float2 bb = *(const float2*)(bias + c);
            float2 o0 = make_float2(acc[t][0] + bb.x, acc[t][1] + bb.y);
            float2 o1 = make_float2(acc[t][2] + bb.x, acc[t][3] + bb.y);
            if (side == 0) {
                __half2 p0 = __floats2half2_rn(o0.x, o0.y);
                __half2 p1 = __floats2half2_rn(o1.x, o1.y);
                if (r0 < NN) xlh[(size_t)r0 * 64 + (c >> 1)] = *(uint32_t*)&p0;
                if (r1 < NN) xlh[(size_t)r1 * 64 + (c >> 1)] = *(uint32_t*)&p1;
            } else {
                if (r0 < NN) *(float2*)(xr + (size_t)r0 * 128 + c) = o0;
                if (r1 < NN) *(float2*)(xr + (size_t)r1 * 128 + c) = o1;
            }
        }
    }
}

// ---------------- readout GEMM (mma.sync) ----------------
template<int KOUT, bool RELU>
__global__ void __launch_bounds__(256) gemmM_k(
    const float* __restrict__ A, const float* __restrict__ W,
    const float* __restrict__ bias, float* __restrict__ C) {
    extern __shared__ __align__(1024) char smem[];
    const int SM_AH = 0;
    const int SM_AL = 16384;
    const int SM_BH = 32768;
    const int SM_BL = 32768 + KOUT * 128;
    constexpr int NT = KOUT / 8;

    uint32_t sb = smem_to_u32(smem);
    int tid  = threadIdx.x;
    int wid  = tid >> 5;
    int lane = tid & 31;
    int n0   = blockIdx.x * 128;

    {
        int n    = tid & 127;
        int half = tid >> 7;
        bool valid = (n0 + n) < NN;
        const float4* ar = (const float4*)(A + (size_t)(n0 + n) * 64);
        uint32_t rowoff = (uint32_t)n * 128;
#pragma unroll
        for (int q = half * 8; q < half * 8 + 8; q += 2) {
            float4 f0 = valid ? __ldg(ar + q)     : make_float4(0.f, 0.f, 0.f, 0.f);
            float4 f1 = valid ? __ldg(ar + q + 1) : make_float4(0.f, 0.f, 0.f, 0.f);
            uint32_t h0, l0, h1, l1, h2, l2, h3, l3;
            split2(f0.x, f0.y, h0, l0);
            split2(f0.z, f0.w, h1, l1);
            split2(f1.x, f1.y, h2, l2);
            split2(f1.z, f1.w, h3, l3);
            uint32_t off = SMEM_SWIZZLE_128B(rowoff + (uint32_t)q * 8);
            *(uint4*)(smem + SM_AH + off) = make_uint4(h0, h1, h2, h3);
            *(uint4*)(smem + SM_AL + off) = make_uint4(l0, l1, l2, l3);
        }
    }
    {
        constexpr int NPAIRS = 32 * KOUT;
#pragma unroll
        for (int pf = tid; pf < NPAIRS; pf += 256) {
            int j2 = pf / KOUT;
            int c  = pf % KOUT;
            float w0 = __ldg(W + (size_t)(2 * j2)     * KOUT + c);
            float w1 = __ldg(W + (size_t)(2 * j2 + 1) * KOUT + c);
            uint32_t hp, lp;
            split2(w0, w1, hp, lp);
            uint32_t off = SMEM_SWIZZLE_128B((uint32_t)c * 128 + (uint32_t)j2 * 4);
            *(uint32_t*)(smem + SM_BH + off) = hp;
            *(uint32_t*)(smem + SM_BL + off) = lp;
        }
    }
    __syncthreads();

    float acc[NT][4];
#pragma unroll
    for (int t = 0; t < NT; t++) {
        acc[t][0] = 0.f; acc[t][1] = 0.f; acc[t][2] = 0.f; acc[t][3] = 0.f;
    }
    uint32_t a_row   = (uint32_t)(wid * 16 + (lane & 15));
    uint32_t a_sel   = (uint32_t)(lane >> 4);
    uint32_t b_row_l = (uint32_t)(lane & 7);
    uint32_t b_sel   = (uint32_t)((lane >> 3) & 1);

#pragma unroll
    for (int ks = 0; ks < 4; ks++) {
        uint32_t ah[4], al[4];
        uint32_t aoff = SMEM_SWIZZLE_128B(a_row * 128 + (uint32_t)(ks * 2 + a_sel) * 16);
        ldm_x4(ah, sb + SM_AH + aoff);
        ldm_x4(al, sb + SM_AL + aoff);
#pragma unroll
        for (int t = 0; t < NT; t++) {
            uint32_t bh[2], bl[2];
            uint32_t boff = SMEM_SWIZZLE_128B(((uint32_t)(t * 8) + b_row_l) * 128 +
                                              (uint32_t)(ks * 2 + b_sel) * 16);
            ldm_x2(bh, sb + SM_BH + boff);
            ldm_x2(bl, sb + SM_BL + boff);
            mma_bf16(acc[t], ah, bh);
            mma_bf16(acc[t], ah, bl);
            mma_bf16(acc[t], al, bh);
        }
    }
    {
        int r0 = n0 + wid * 16 + (lane >> 2);
        int r1 = r0 + 8;
#pragma unroll
        for (int t = 0; t < NT; t++) {
            int c = t * 8 + 2 * (lane & 3);
            float2 bb = *(const float2*)(bias + c);
            float2 o0 = make_float2(acc[t][0] + bb.x, acc[t][1] + bb.y);
            float2 o1 = make_float2(acc[t][2] + bb.x, acc[t][3] + bb.y);
            if (RELU) {
                o0.x = fmaxf(o0.x, 0.f); o0.y = fmaxf(o0.y, 0.f);
                o1.x = fmaxf(o1.x, 0.f); o1.y = fmaxf(o1.y, 0.f);
            }
            if (r0 < NN) *(float2*)(C + (size_t)r0 * KOUT + c) = o0;
            if (r1 < NN) *(float2*)(C + (size_t)r1 * KOUT + c) = o1;
        }
    }
}

// ---------------- GATv2: one warp per dst, half-precision messages ----------------
__global__ void gat_k(const uint32_t* __restrict__ xlh, const float* __restrict__ xr,
                      const float* __restrict__ att, const float* __restrict__ bias,
                      float* __restrict__ hout) {
    int gw = (blockIdx.x * blockDim.x + threadIdx.x) >> 5;
    if (gw >= NN) return;
    int lane = threadIdx.x & 31;
    int dst = gw;

    float4 xr4 = *(const float4*)(xr + dst * 128 + lane * 4);
    float4 at4 = *(const float4*)(att + lane * 4);

    int beg = __ldg(g_rowoff + dst), end = __ldg(g_rowoff + dst + 1);

    float m = -1e30f, s = 0.f;
    float ax = 0.f, ay = 0.f, az = 0.f, aw = 0.f;

    for (int i = beg; i < end; i += 4) {
        float p[4];
        float4 xs[4];
#pragma unroll
        for (int k = 0; k < 4; k++) {
            bool valid = (i + k) < end;
            int src = valid ? __ldg(g_csrsrc + i + k) : 0;
            uint2 wv = __ldg((const uint2*)(xlh + (size_t)src * 64 + lane * 2));
            float2 f0 = __half22float2(*(__half2*)&wv.x);
            float2 f1 = __half22float2(*(__half2*)&wv.y);
            xs[k] = make_float4(f0.x, f0.y, f1.x, f1.y);
            float vx = xs[k].x + xr4.x, vy = xs[k].y + xr4.y;
            float vz = xs[k].z + xr4.z, vw = xs[k].w + xr4.w;
            vx = vx > 0.f ? vx : 0.2f * vx;
            vy = vy > 0.f ? vy : 0.2f * vy;
            vz = vz > 0.f ? vz : 0.2f * vz;
            vw = vw > 0.f ? vw : 0.2f * vw;
            float pk = vx * at4.x + vy * at4.y + vz * at4.z + vw * at4.w;
            p[k] = valid ? pk : -1e30f;
        }
#pragma unroll
        for (int k = 0; k < 4; k++) {
            float pk = p[k];
            pk += __shfl_xor_sync(0xffffffffu, pk, 1);
            pk += __shfl_xor_sync(0xffffffffu, pk, 2);
            pk += __shfl_xor_sync(0xffffffffu, pk, 4);
            pk += __shfl_xor_sync(0xffffffffu, pk, 8);
            p[k] = ((i + k) < end) ? pk : -1e30f;
        }
        float mb = fmaxf(fmaxf(p[0], p[1]), fmaxf(p[2], p[3]));
        float mn = fmaxf(m, mb);
        float r  = __expf(m - mn);
        float w0 = __expf(p[0] - mn);
        float w1 = __expf(p[1] - mn);
        float w2 = __expf(p[2] - mn);
        float w3 = __expf(p[3] - mn);
        s  = s * r + ((w0 + w1) + (w2 + w3));
        ax = ax * r + w0 * xs[0].x + w1 * xs[1].x + w2 * xs[2].x + w3 * xs[3].x;
        ay = ay * r + w0 * xs[0].y + w1 * xs[1].y + w2 * xs[2].y + w3 * xs[3].y;
        az = az * r + w0 * xs[0].z + w1 * xs[1].z + w2 * xs[2].z + w3 * xs[3].z;
        aw = aw * r + w0 * xs[0].w + w1 * xs[1].w + w2 * xs[2].w + w3 * xs[3].w;
        m = mn;
    }

    float inv = 1.f / s;
    ax *= inv; ay *= inv; az *= inv; aw *= inv;

    float bx = ax + __shfl_xor_sync(0xffffffffu, ax, 16);
    float by = ay + __shfl_xor_sync(0xffffffffu, ay, 16);
    float bz = az + __shfl_xor_sync(0xffffffffu, az, 16);
    float bw = aw + __shfl_xor_sync(0xffffffffu, aw, 16);

    if (lane < 16) {
        float4 b4 = *(const float4*)(bias + lane * 4);
        float4 o = make_float4(0.5f * bx + b4.x, 0.5f * by + b4.y,
                               0.5f * bz + b4.z, 0.5f * bw + b4.w);
        *(float4*)(hout + dst * 64 + lane * 4) = o;
    }
}

// ---------------- output zero + graph segment-sum ----------------
__global__ void zero_k(float* __restrict__ out) {
    int t = blockIdx.x * blockDim.x + threadIdx.x;
    if (t < GG * 128 / 4)
        *(float4*)(out + t * 4) = make_float4(0.f, 0.f, 0.f, 0.f);
}

__global__ void segsum_k(const int* __restrict__ batch, const float* __restrict__ outn,
                         float* __restrict__ out) {
    int t = blockIdx.x * blockDim.x + threadIdx.x;
    if (t >= NN * 32) return;
    int n = t >> 5, q = t & 31;
    float4 v = *(const float4*)(outn + n * 128 + q * 4);
    int g = batch[n];
    float* p = out + g * 128 + q * 4;
    atomicAdd(p + 0, v.x);
    atomicAdd(p + 1, v.y);
    atomicAdd(p + 2, v.z);
    atomicAdd(p + 3, v.w);
}

// ---------------- launcher ----------------
extern "C" void kernel_launch(void* const* d_in, const int* in_sizes, int n_in,
                              void* d_out, int out_size) {
    const int* x     = (const int*)d_in[0];
    const int* ei    = (const int*)d_in[1];
    const int* batch = (const int*)d_in[2];
    int base = (in_sizes[3] == 1) ? 4 : 3;
    const float* embed = (const float*)d_in[base + 0];
    const float* lin_W = (const float*)d_in[base + 1];
    const float* lin_b = (const float*)d_in[base + 2];
    const float* gWl   = (const float*)d_in[base + 3];
    const float* gbl   = (const float*)d_in[base + 4];
    const float* gWr   = (const float*)d_in[base + 5];
    const float* gbr   = (const float*)d_in[base + 6];
    const float* gatt  = (const float*)d_in[base + 7];
    const float* gbias = (const float*)d_in[base + 8];
    const float* rW    = (const float*)d_in[base + 9];
    const float* rb    = (const float*)d_in[base + 10];
    float* out = (float*)d_out;

    void* ph  = 0;
    void* pxl = 0;
    void* pxr = 0;
    void* pro = 0;
    cudaGetSymbolAddress(&ph,  g_h);
    cudaGetSymbolAddress(&pxl, g_xlh);
    cudaGetSymbolAddress(&pxr, g_xr);
    cudaGetSymbolAddress(&pro, g_ro);
    float*    h   = (float*)ph;
    uint32_t* xlh = (uint32_t*)pxl;
    float*    xr  = (float*)pxr;
    float*    ro  = (float*)pro;

    const int SMEM_FUSED = 147456;                 // 144KB
    const int SMEM128    = 32768 + 128 * 256;      // 65536
    cudaFuncSetAttribute(fused_layer_k, cudaFuncAttributeMaxDynamicSharedMemorySize, SMEM_FUSED);
    cudaFuncSetAttribute(gemmM_k<128, false>, cudaFuncAttributeMaxDynamicSharedMemorySize, SMEM128);

    // launches 1-3 (keeps fused kernel in ncu capture slot 4)
    embed_k<<<(NN * 16 + 255) / 256, 256>>>(x, embed);   // also inits g_deg
    hist_k<<<(EE + 255) / 256, 256>>>(ei);
    blocksum_k<<<NBLK, 256>>>();

    // launch 4 = fused layer 0 (capture slot)
    fused_layer_k<<<GTB, 512, SMEM_FUSED>>>(h, lin_W, lin_b, gWl, gbl, gWr, gbr, xlh, xr);

    // finish CSR build (needed only by gat_k)
    bscan_k<<<1, 256>>>();
    scatter_scan_k<<<NBLK, 256>>>();
    fill_k<<<(EN + 255) / 256, 256>>>(ei);

    gat_k<<<(NN + 7) / 8, 256>>>(xlh, xr, gatt, gbias, h);

    for (int l = 1; l < 3; l++) {
        fused_layer_k<<<GTB, 512, SMEM_FUSED>>>(h, lin_W + l * 64 * 64, lin_b + l * 64,
                                                gWl + l * 64 * 128, gbl + l * 128,
                                                gWr + l * 64 * 128, gbr + l * 128, xlh, xr);
        gat_k<<<(NN + 7) / 8, 256>>>(xlh, xr, gatt + l * 128, gbias + l * 64, h);
    }

    gemmM_k<128, false><<<GTB, 256, SMEM128>>>(h, rW, rb, ro);
    zero_k<<<(GG * 128 / 4 + 255) / 256, 256>>>(out);
    segsum_k<<<(NN * 32 + 255) / 256, 256>>>(batch, ro, out);
}

// round 15
// speedup vs baseline: 1.0513x; 1.0513x over previous
#include <cuda_runtime.h>
#include <cuda.h>
#include <cuda_fp16.h>
#include <cstdint>
#include <cstddef>

#define NN 50000
#define EE 800000
#define EN 850000   // EE + NN (self loops)
#define GG 512
#define NBLK 196    // ceil(NN/256)
#define GTB  391    // ceil(NN/128) node tiles for tensor GEMM

// ---------------- scratch (static device globals; no allocation) ----------------
__device__ __align__(16) float    g_h  [NN * 64];
__device__ __align__(16) uint32_t g_xlh[NN * 64];   // xl as half2-packed [N][128]
__device__ __align__(16) float    g_xr [NN * 128];
__device__ __align__(16) float    g_ro [NN * 128];  // readout scratch
__device__ int   g_deg[NN];
__device__ int   g_rowoff[NN + 1];
__device__ int   g_cursor[NN];
__device__ int   g_csrsrc[EN];
__device__ int   g_bsum[256];

// ---------------- helpers ----------------
__device__ __forceinline__ uint32_t smem_to_u32(const void* smem_ptr) {
    uint32_t addr;
    asm("{ .reg .u64 tmp; cvta.to.shared.u64 tmp, %1; cvt.u32.u64 %0, tmp; }"
        : "=r"(addr) : "l"(smem_ptr));
    return addr;
}

#define SMEM_SWIZZLE_128B(byte_offset) \
    ((byte_offset) ^ (((byte_offset) >> 3) & 0x70))

__device__ __forceinline__ uint32_t bf2(float lo, float hi) {
    uint32_t r;
    asm("cvt.rn.bf16x2.f32 %0, %1, %2;" : "=r"(r) : "f"(hi), "f"(lo));
    return r;
}
__device__ __forceinline__ float bflo(uint32_t p) { return __uint_as_float(p << 16); }
__device__ __forceinline__ float bfhi(uint32_t p) { return __uint_as_float(p & 0xffff0000u); }

__device__ __forceinline__ void ldm_x4(uint32_t* r, uint32_t addr) {
    asm volatile("ldmatrix.sync.aligned.m8n8.x4.shared.b16 {%0,%1,%2,%3}, [%4];"
        : "=r"(r[0]), "=r"(r[1]), "=r"(r[2]), "=r"(r[3]) : "r"(addr));
}
__device__ __forceinline__ void ldm_x2(uint32_t* r, uint32_t addr) {
    asm volatile("ldmatrix.sync.aligned.m8n8.x2.shared.b16 {%0,%1}, [%2];"
        : "=r"(r[0]), "=r"(r[1]) : "r"(addr));
}
__device__ __forceinline__ void mma_bf16(float* d, const uint32_t* a, const uint32_t* b) {
    asm volatile(
        "mma.sync.aligned.m16n8k16.row.col.f32.bf16.bf16.f32 "
        "{%0,%1,%2,%3}, {%4,%5,%6,%7}, {%8,%9}, {%0,%1,%2,%3};"
        : "+f"(d[0]), "+f"(d[1]), "+f"(d[2]), "+f"(d[3])
        : "r"(a[0]), "r"(a[1]), "r"(a[2]), "r"(a[3]), "r"(b[0]), "r"(b[1]));
}

__device__ __forceinline__ void split2(float x, float y, uint32_t& hp, uint32_t& lp) {
    hp = bf2(x, y);
    lp = bf2(x - bflo(hp), y - bfhi(hp));
}

// ---------------- embedding gather (+ deg init fused) ----------------
__global__ void embed_k(const int* __restrict__ x, const float* __restrict__ embed) {
    int t = blockIdx.x * blockDim.x + threadIdx.x;
    if (t >= NN * 16) return;
    int n = t >> 4, q = t & 15;
    if (q == 0) g_deg[n] = 1;
    int row = x[n];
    float4 v = *(const float4*)(embed + row * 64 + q * 4);
    *(float4*)(g_h + n * 64 + q * 4) = v;
}

// ---------------- CSR build ----------------
__global__ void hist_k(const int* __restrict__ ei) {
    int e = blockIdx.x * blockDim.x + threadIdx.x;
    if (e >= EE) return;
    atomicAdd(&g_deg[ei[EE + e]], 1);
}

__global__ void blocksum_k() {
    __shared__ int sh[8];
    int i = blockIdx.x * 256 + threadIdx.x;
    int v = (i < NN) ? g_deg[i] : 0;
#pragma unroll
    for (int o = 16; o; o >>= 1) v += __shfl_down_sync(0xffffffffu, v, o);
    if ((threadIdx.x & 31) == 0) sh[threadIdx.x >> 5] = v;
    __syncthreads();
    if (threadIdx.x == 0) {
        int s = 0;
#pragma unroll
        for (int w = 0; w < 8; w++) s += sh[w];
        g_bsum[blockIdx.x] = s;
    }
}

__global__ void bscan_k() {
    __shared__ int sh[256];
    int t = threadIdx.x;
    int v = (t < NBLK) ? g_bsum[t] : 0;
    sh[t] = v;
    __syncthreads();
#pragma unroll
    for (int off = 1; off < 256; off <<= 1) {
        int add = (t >= off) ? sh[t - off] : 0;
        __syncthreads();
        sh[t] += add;
        __syncthreads();
    }
    if (t < NBLK) g_bsum[t] = (t == 0) ? 0 : sh[t - 1];
    if (t == 0) g_rowoff[NN] = EN;
}

__global__ void scatter_scan_k() {
    __shared__ int sh[256];
    int t = threadIdx.x;
    int i = blockIdx.x * 256 + t;
    int v = (i < NN) ? g_deg[i] : 0;
    sh[t] = v;
    __syncthreads();
#pragma unroll
    for (int off = 1; off < 256; off <<= 1) {
        int add = (t >= off) ? sh[t - off] : 0;
        __syncthreads();
        sh[t] += add;
        __syncthreads();
    }
    int excl = ((t == 0) ? 0 : sh[t - 1]) + g_bsum[blockIdx.x];
    if (i < NN) { g_rowoff[i] = excl; g_cursor[i] = excl; }
}

__global__ void fill_k(const int* __restrict__ ei) {
    int t = blockIdx.x * blockDim.x + threadIdx.x;
    if (t >= EN) return;
    int s, d;
    if (t < EE) { s = ei[t]; d = ei[EE + t]; }
    else        { s = t - EE; d = s; }
    int pos = atomicAdd(&g_cursor[d], 1);
    g_csrsrc[pos] = s;
}

// ---------------- fused layer kernel: lin -> (xl half, xr fp32) ----------------
__global__ void __launch_bounds__(512) fused_layer_k(
    const float* __restrict__ h, const float* __restrict__ linW,
    const float* __restrict__ lin_b, const float* __restrict__ Wl,
    const float* __restrict__ bl, const float* __restrict__ Wr,
    const float* __restrict__ br,
    uint32_t* __restrict__ xlh, float* __restrict__ xr) {
    extern __shared__ __align__(1024) char smem[];
    const int A_H  = 0,       A_L  = 16384;    // h tile      128x64 bf16
    const int LW_H = 32768,   LW_L = 40960;    // linW        64x64  bf16 (Bt layout)
    const int A2_H = 49152,   A2_L = 65536;    // lin result  128x64 bf16
    const int BL_H = 81920,   BL_L = 98304;    // Wl          128x64 bf16 (Bt layout)
    const int BR_H = 114688,  BR_L = 131072;   // Wr

    uint32_t sb = smem_to_u32(smem);
    int tid  = threadIdx.x;                    // 0..511
    int wid  = tid >> 5;                       // 0..15
    int lane = tid & 31;
    int n0   = blockIdx.x * 128;

    // ---- stage A = h hi/lo ----
    {
        int n  = tid & 127;
        int q4 = tid >> 7;                     // 0..3
        bool valid = (n0 + n) < NN;
        const float4* ar = (const float4*)(h + (size_t)(n0 + n) * 64);
        uint32_t rowoff = (uint32_t)n * 128;
#pragma unroll
        for (int q = q4 * 4; q < q4 * 4 + 4; q += 2) {
            float4 f0 = valid ? __ldg(ar + q)     : make_float4(0.f, 0.f, 0.f, 0.f);
            float4 f1 = valid ? __ldg(ar + q + 1) : make_float4(0.f, 0.f, 0.f, 0.f);
            uint32_t h0, l0, h1, l1, h2, l2, h3, l3;
            split2(f0.x, f0.y, h0, l0);
            split2(f0.z, f0.w, h1, l1);
            split2(f1.x, f1.y, h2, l2);
            split2(f1.z, f1.w, h3, l3);
            uint32_t off = SMEM_SWIZZLE_128B(rowoff + (uint32_t)q * 8);
            *(uint4*)(smem + A_H + off) = make_uint4(h0, h1, h2, h3);
            *(uint4*)(smem + A_L + off) = make_uint4(l0, l1, l2, l3);
        }
    }
    // ---- stage linW hi/lo ----
#pragma unroll
    for (int pf = tid; pf < 32 * 64; pf += 512) {
        int j2 = pf >> 6, c = pf & 63;
        float w0 = __ldg(linW + (size_t)(2 * j2)     * 64 + c);
        float w1 = __ldg(linW + (size_t)(2 * j2 + 1) * 64 + c);
        uint32_t hp, lp;
        split2(w0, w1, hp, lp);
        uint32_t off = SMEM_SWIZZLE_128B((uint32_t)c * 128 + (uint32_t)j2 * 4);
        *(uint32_t*)(smem + LW_H + off) = hp;
        *(uint32_t*)(smem + LW_L + off) = lp;
    }
    // ---- stage Wl, Wr hi/lo ----
#pragma unroll
    for (int pf = tid; pf < 32 * 128; pf += 512) {
        int j2 = pf >> 7, c = pf & 127;
        uint32_t off = SMEM_SWIZZLE_128B((uint32_t)c * 128 + (uint32_t)j2 * 4);
        float w0 = __ldg(Wl + (size_t)(2 * j2)     * 128 + c);
        float w1 = __ldg(Wl + (size_t)(2 * j2 + 1) * 128 + c);
        uint32_t hp, lp;
        split2(w0, w1, hp, lp);
        *(uint32_t*)(smem + BL_H + off) = hp;
        *(uint32_t*)(smem + BL_L + off) = lp;
        w0 = __ldg(Wr + (size_t)(2 * j2)     * 128 + c);
        w1 = __ldg(Wr + (size_t)(2 * j2 + 1) * 128 + c);
        split2(w0, w1, hp, lp);
        *(uint32_t*)(smem + BR_H + off) = hp;
        *(uint32_t*)(smem + BR_L + off) = lp;
    }
    __syncthreads();

    uint32_t a_sel   = (uint32_t)(lane >> 4);
    uint32_t b_row_l = (uint32_t)(lane & 7);
    uint32_t b_sel   = (uint32_t)((lane >> 3) & 1);

    // ---- phase 1: lin tile ----
    {
        int rg = (wid & 7) * 16;
        int ch = wid >> 3;
        float acc[4][4];
#pragma unroll
        for (int t = 0; t < 4; t++) {
            acc[t][0] = 0.f; acc[t][1] = 0.f; acc[t][2] = 0.f; acc[t][3] = 0.f;
        }
        uint32_t a_row = (uint32_t)(rg + (lane & 15));
#pragma unroll
        for (int ks = 0; ks < 4; ks++) {
            uint32_t ah[4], al[4];
            uint32_t aoff = SMEM_SWIZZLE_128B(a_row * 128 + (uint32_t)(ks * 2 + a_sel) * 16);
            ldm_x4(ah, sb + A_H + aoff);
            ldm_x4(al, sb + A_L + aoff);
#pragma unroll
            for (int t = 0; t < 4; t++) {
                uint32_t bh[2], blo[2];
                uint32_t boff = SMEM_SWIZZLE_128B(((uint32_t)(ch * 32 + t * 8) + b_row_l) * 128 +
                                                  (uint32_t)(ks * 2 + b_sel) * 16);
                ldm_x2(bh,  sb + LW_H + boff);
                ldm_x2(blo, sb + LW_L + boff);
                mma_bf16(acc[t], ah, bh);
                mma_bf16(acc[t], ah, blo);
                mma_bf16(acc[t], al, bh);
            }
        }
        int r0 = rg + (lane >> 2);
        int r1 = r0 + 8;
#pragma unroll
        for (int t = 0; t < 4; t++) {
            int c = ch * 32 + t * 8 + 2 * (lane & 3);
            float2 bb = *(const float2*)(lin_b + c);
            float o0x = fmaxf(acc[t][0] + bb.x, 0.f);
            float o0y = fmaxf(acc[t][1] + bb.y, 0.f);
            float o1x = fmaxf(acc[t][2] + bb.x, 0.f);
            float o1y = fmaxf(acc[t][3] + bb.y, 0.f);
            uint32_t hp, lp;
            split2(o0x, o0y, hp, lp);
            uint32_t off0 = SMEM_SWIZZLE_128B((uint32_t)r0 * 128 + (uint32_t)c * 2);
            *(uint32_t*)(smem + A2_H + off0) = hp;
            *(uint32_t*)(smem + A2_L + off0) = lp;
            split2(o1x, o1y, hp, lp);
            uint32_t off1 = SMEM_SWIZZLE_128B((uint32_t)r1 * 128 + (uint32_t)c * 2);
            *(uint32_t*)(smem + A2_H + off1) = hp;
            *(uint32_t*)(smem + A2_L + off1) = lp;
        }
    }
    __syncthreads();

    // ---- phase 2: warps 0-7 -> xl (half2 packed); warps 8-15 -> xr (fp32) ----
    {
        int side = wid >> 3;
        int rg   = (wid & 7) * 16;
        const int B_H = side ? BR_H : BL_H;
        const int B_L = side ? BR_L : BL_L;
        const float* bias = side ? br : bl;

        float acc[16][4];
#pragma unroll
        for (int t = 0; t < 16; t++) {
            acc[t][0] = 0.f; acc[t][1] = 0.f; acc[t][2] = 0.f; acc[t][3] = 0.f;
        }
        uint32_t a_row = (uint32_t)(rg + (lane & 15));
#pragma unroll
        for (int ks = 0; ks < 4; ks++) {
            uint32_t ah[4], al[4];
            uint32_t aoff = SMEM_SWIZZLE_128B(a_row * 128 + (uint32_t)(ks * 2 + a_sel) * 16);
            ldm_x4(ah, sb + A2_H + aoff);
            ldm_x4(al, sb + A2_L + aoff);
#pragma unroll
            for (int t = 0; t < 16; t++) {
                uint32_t bh[2], blo[2];
                uint32_t boff = SMEM_SWIZZLE_128B(((uint32_t)(t * 8) + b_row_l) * 128 +
                                                  (uint32_t)(ks * 2 + b_sel) * 16);
                ldm_x2(bh,  sb + B_H + boff);
                ldm_x2(blo, sb + B_L + boff);
                mma_bf16(acc[t], ah, bh);
                mma_bf16(acc[t], ah, blo);
                mma_bf16(acc[t], al, bh);
            }
        }
        int r0 = n0 + rg + (lane >> 2);
        int r1 = r0 + 8;
#pragma unroll
        for (int t = 0; t < 16; t++) {
            int c = t * 8 + 2 * (lane & 3);
            float2 bb = *(const float2*)(bias + c);
            float2 o0 = make_float2(acc[t][0] + bb.x, acc[t][1] + bb.y);
            float2 o1 = make_float2(acc[t][2] + bb.x, acc[t][3] + bb.y);
            if (side == 0) {
                __half2 p0 = __floats2half2_rn(o0.x, o0.y);
                __half2 p1 = __floats2half2_rn(o1.x, o1.y);
                if (r0 < NN) xlh[(size_t)r0 * 64 + (c >> 1)] = *(uint32_t*)&p0;
                if (r1 < NN) xlh[(size_t)r1 * 64 + (c >> 1)] = *(uint32_t*)&p1;
            } else {
                if (r0 < NN) *(float2*)(xr + (size_t)r0 * 128 + c) = o0;
                if (r1 < NN) *(float2*)(xr + (size_t)r1 * 128 + c) = o1;
            }
        }
    }
}

// ---------------- readout GEMM (mma.sync) ----------------
template<int KOUT, bool RELU>
__global__ void __launch_bounds__(256) gemmM_k(
    const float* __restrict__ A, const float* __restrict__ W,
    const float* __restrict__ bias, float* __restrict__ C) {
    extern __shared__ __align__(1024) char smem[];
    const int SM_AH = 0;
    const int SM_AL = 16384;
    const int SM_BH = 32768;
    const int SM_BL = 32768 + KOUT * 128;
    constexpr int NT = KOUT / 8;

    uint32_t sb = smem_to_u32(smem);
    int tid  = threadIdx.x;
    int wid  = tid >> 5;
    int lane = tid & 31;
    int n0   = blockIdx.x * 128;

    {
        int n    = tid & 127;
        int half = tid >> 7;
        bool valid = (n0 + n) < NN;
        const float4* ar = (const float4*)(A + (size_t)(n0 + n) * 64);
        uint32_t rowoff = (uint32_t)n * 128;
#pragma unroll
        for (int q = half * 8; q < half * 8 + 8; q += 2) {
            float4 f0 = valid ? __ldg(ar + q)     : make_float4(0.f, 0.f, 0.f, 0.f);
            float4 f1 = valid ? __ldg(ar + q + 1) : make_float4(0.f, 0.f, 0.f, 0.f);
            uint32_t h0, l0, h1, l1, h2, l2, h3, l3;
            split2(f0.x, f0.y, h0, l0);
            split2(f0.z, f0.w, h1, l1);
            split2(f1.x, f1.y, h2, l2);
            split2(f1.z, f1.w, h3, l3);
            uint32_t off = SMEM_SWIZZLE_128B(rowoff + (uint32_t)q * 8);
            *(uint4*)(smem + SM_AH + off) = make_uint4(h0, h1, h2, h3);
            *(uint4*)(smem + SM_AL + off) = make_uint4(l0, l1, l2, l3);
        }
    }
    {
        constexpr int NPAIRS = 32 * KOUT;
#pragma unroll
        for (int pf = tid; pf < NPAIRS; pf += 256) {
            int j2 = pf / KOUT;
            int c  = pf % KOUT;
            float w0 = __ldg(W + (size_t)(2 * j2)     * KOUT + c);
            float w1 = __ldg(W + (size_t)(2 * j2 + 1) * KOUT + c);
            uint32_t hp, lp;
            split2(w0, w1, hp, lp);
            uint32_t off = SMEM_SWIZZLE_128B((uint32_t)c * 128 + (uint32_t)j2 * 4);
            *(uint32_t*)(smem + SM_BH + off) = hp;
            *(uint32_t*)(smem + SM_BL + off) = lp;
        }
    }
    __syncthreads();

    float acc[NT][4];
#pragma unroll
    for (int t = 0; t < NT; t++) {
        acc[t][0] = 0.f; acc[t][1] = 0.f; acc[t][2] = 0.f; acc[t][3] = 0.f;
    }
    uint32_t a_row   = (uint32_t)(wid * 16 + (lane & 15));
    uint32_t a_sel   = (uint32_t)(lane >> 4);
    uint32_t b_row_l = (uint32_t)(lane & 7);
    uint32_t b_sel   = (uint32_t)((lane >> 3) & 1);

#pragma unroll
    for (int ks = 0; ks < 4; ks++) {
        uint32_t ah[4], al[4];
        uint32_t aoff = SMEM_SWIZZLE_128B(a_row * 128 + (uint32_t)(ks * 2 + a_sel) * 16);
        ldm_x4(ah, sb + SM_AH + aoff);
        ldm_x4(al, sb + SM_AL + aoff);
#pragma unroll
        for (int t = 0; t < NT; t++) {
            uint32_t bh[2], bl[2];
            uint32_t boff = SMEM_SWIZZLE_128B(((uint32_t)(t * 8) + b_row_l) * 128 +
                                              (uint32_t)(ks * 2 + b_sel) * 16);
            ldm_x2(bh, sb + SM_BH + boff);
            ldm_x2(bl, sb + SM_BL + boff);
            mma_bf16(acc[t], ah, bh);
            mma_bf16(acc[t], ah, bl);
            mma_bf16(acc[t], al, bh);
        }
    }
    {
        int r0 = n0 + wid * 16 + (lane >> 2);
        int r1 = r0 + 8;
#pragma unroll
        for (int t = 0; t < NT; t++) {
            int c = t * 8 + 2 * (lane & 3);
            float2 bb = *(const float2*)(bias + c);
            float2 o0 = make_float2(acc[t][0] + bb.x, acc[t][1] + bb.y);
            float2 o1 = make_float2(acc[t][2] + bb.x, acc[t][3] + bb.y);
            if (RELU) {
                o0.x = fmaxf(o0.x, 0.f); o0.y = fmaxf(o0.y, 0.f);
                o1.x = fmaxf(o1.x, 0.f); o1.y = fmaxf(o1.y, 0.f);
            }
            if (r0 < NN) *(float2*)(C + (size_t)r0 * KOUT + c) = o0;
            if (r1 < NN) *(float2*)(C + (size_t)r1 * KOUT + c) = o1;
        }
    }
}

// ---------------- GATv2: TWO dsts per warp (16 lanes each), 4-edge batching ----------------
// lane = 16*half + hl. hl covers 8 channels: head (hl>>3), channels (hl&7)*8..+7.
// Score reduce: xor 1,2,4 within the 8-lane head group. Head mean: xor 8.
__global__ void gat_k(const uint32_t* __restrict__ xlh, const float* __restrict__ xr,
                      const float* __restrict__ att, const float* __restrict__ bias,
                      float* __restrict__ hout) {
    int warp = (blockIdx.x * blockDim.x + threadIdx.x) >> 5;
    if (warp >= (NN + 1) / 2) return;
    int lane = threadIdx.x & 31;
    int hl   = lane & 15;
    int dst  = warp * 2 + (lane >> 4);
    if (dst >= NN) dst = NN - 1;                 // duplicate work on tail; harmless rewrite

    int chf = (hl >> 3) * 64 + (hl & 7) * 8;     // float channel offset (8 channels)
    int chp = chf >> 1;                          // uint32 pair index within 64-wide row

    float xrv[8], atv[8];
    {
        float4 x0 = *(const float4*)(xr + (size_t)dst * 128 + chf);
        float4 x1 = *(const float4*)(xr + (size_t)dst * 128 + chf + 4);
        xrv[0] = x0.x; xrv[1] = x0.y; xrv[2] = x0.z; xrv[3] = x0.w;
        xrv[4] = x1.x; xrv[5] = x1.y; xrv[6] = x1.z; xrv[7] = x1.w;
        float4 a0 = __ldg((const float4*)(att + chf));
        float4 a1 = __ldg((const float4*)(att + chf + 4));
        atv[0] = a0.x; atv[1] = a0.y; atv[2] = a0.z; atv[3] = a0.w;
        atv[4] = a1.x; atv[5] = a1.y; atv[6] = a1.z; atv[7] = a1.w;
    }

    int beg = __ldg(g_rowoff + dst), end = __ldg(g_rowoff + dst + 1);
    int len = end - beg;
    int maxlen = max(len, __shfl_xor_sync(0xffffffffu, len, 16));

    float m = -1e30f, s = 0.f;
    float acc[8];
#pragma unroll
    for (int j = 0; j < 8; j++) acc[j] = 0.f;

    for (int i = 0; i < maxlen; i += 4) {
        float p[4];
        float xsv[4][8];
#pragma unroll
        for (int k = 0; k < 4; k++) {
            bool valid = (i + k) < len;
            int src = valid ? __ldg(g_csrsrc + beg + i + k) : dst;
            uint4 wv = __ldg((const uint4*)(xlh + (size_t)src * 64 + chp));
            float2 f0 = __half22float2(*(__half2*)&wv.x);
            float2 f1 = __half22float2(*(__half2*)&wv.y);
            float2 f2 = __half22float2(*(__half2*)&wv.z);
            float2 f3 = __half22float2(*(__half2*)&wv.w);
            xsv[k][0] = f0.x; xsv[k][1] = f0.y; xsv[k][2] = f1.x; xsv[k][3] = f1.y;
            xsv[k][4] = f2.x; xsv[k][5] = f2.y; xsv[k][6] = f3.x; xsv[k][7] = f3.y;
            float pk = 0.f;
#pragma unroll
            for (int j = 0; j < 8; j++) {
                float v = xsv[k][j] + xrv[j];
                v = v > 0.f ? v : 0.2f * v;
                pk += v * atv[j];
            }
            p[k] = pk;
        }
#pragma unroll
        for (int k = 0; k < 4; k++) {
            float pk = p[k];
            pk += __shfl_xor_sync(0xffffffffu, pk, 1);
            pk += __shfl_xor_sync(0xffffffffu, pk, 2);
            pk += __shfl_xor_sync(0xffffffffu, pk, 4);
            p[k] = ((i + k) < len) ? pk : -1e30f;
        }
        float mb = fmaxf(fmaxf(p[0], p[1]), fmaxf(p[2], p[3]));
        float mn = fmaxf(m, mb);
        float r  = __expf(m - mn);
        float w0 = __expf(p[0] - mn);
        float w1 = __expf(p[1] - mn);
        float w2 = __expf(p[2] - mn);
        float w3 = __expf(p[3] - mn);
        s = s * r + ((w0 + w1) + (w2 + w3));
#pragma unroll
        for (int j = 0; j < 8; j++) {
            acc[j] = acc[j] * r + w0 * xsv[0][j] + w1 * xsv[1][j]
                               + w2 * xsv[2][j] + w3 * xsv[3][j];
        }
        m = mn;
    }

    float inv = 1.f / s;
#pragma unroll
    for (int j = 0; j < 8; j++) acc[j] *= inv;

    // mean over the two heads: partner lane hl ^ 8 (same half-warp)
    float bx[8];
#pragma unroll
    for (int j = 0; j < 8; j++)
        bx[j] = acc[j] + __shfl_xor_sync(0xffffffffu, acc[j], 8);

    if (hl < 8) {
        int cb = hl * 8;
        float4 b0 = __ldg((const float4*)(bias + cb));
        float4 b1 = __ldg((const float4*)(bias + cb + 4));
        float4 o0 = make_float4(0.5f * bx[0] + b0.x, 0.5f * bx[1] + b0.y,
                                0.5f * bx[2] + b0.z, 0.5f * bx[3] + b0.w);
        float4 o1 = make_float4(0.5f * bx[4] + b1.x, 0.5f * bx[5] + b1.y,
                                0.5f * bx[6] + b1.z, 0.5f * bx[7] + b1.w);
        *(float4*)(hout + (size_t)dst * 64 + cb)     = o0;
        *(float4*)(hout + (size_t)dst * 64 + cb + 4) = o1;
    }
}

// ---------------- output zero + graph segment-sum ----------------
__global__ void zero_k(float* __restrict__ out) {
    int t = blockIdx.x * blockDim.x + threadIdx.x;
    if (t < GG * 128 / 4)
        *(float4*)(out + t * 4) = make_float4(0.f, 0.f, 0.f, 0.f);
}

__global__ void segsum_k(const int* __restrict__ batch, const float* __restrict__ outn,
                         float* __restrict__ out) {
    int t = blockIdx.x * blockDim.x + threadIdx.x;
    if (t >= NN * 32) return;
    int n = t >> 5, q = t & 31;
    float4 v = *(const float4*)(outn + n * 128 + q * 4);
    int g = batch[n];
    float* p = out + g * 128 + q * 4;
    atomicAdd(p + 0, v.x);
    atomicAdd(p + 1, v.y);
    atomicAdd(p + 2, v.z);
    atomicAdd(p + 3, v.w);
}

// ---------------- launcher ----------------
extern "C" void kernel_launch(void* const* d_in, const int* in_sizes, int n_in,
                              void* d_out, int out_size) {
    const int* x     = (const int*)d_in[0];
    const int* ei    = (const int*)d_in[1];
    const int* batch = (const int*)d_in[2];
    int base = (in_sizes[3] == 1) ? 4 : 3;
    const float* embed = (const float*)d_in[base + 0];
    const float* lin_W = (const float*)d_in[base + 1];
    const float* lin_b = (const float*)d_in[base + 2];
    const float* gWl   = (const float*)d_in[base + 3];
    const float* gbl   = (const float*)d_in[base + 4];
    const float* gWr   = (const float*)d_in[base + 5];
    const float* gbr   = (const float*)d_in[base + 6];
    const float* gatt  = (const float*)d_in[base + 7];
    const float* gbias = (const float*)d_in[base + 8];
    const float* rW    = (const float*)d_in[base + 9];
    const float* rb    = (const float*)d_in[base + 10];
    float* out = (float*)d_out;

    void* ph  = 0;
    void* pxl = 0;
    void* pxr = 0;
    void* pro = 0;
    cudaGetSymbolAddress(&ph,  g_h);
    cudaGetSymbolAddress(&pxl, g_xlh);
    cudaGetSymbolAddress(&pxr, g_xr);
    cudaGetSymbolAddress(&pro, g_ro);
    float*    h   = (float*)ph;
    uint32_t* xlh = (uint32_t*)pxl;
    float*    xr  = (float*)pxr;
    float*    ro  = (float*)pro;

    const int SMEM_FUSED = 147456;                 // 144KB
    const int SMEM128    = 32768 + 128 * 256;      // 65536
    cudaFuncSetAttribute(fused_layer_k, cudaFuncAttributeMaxDynamicSharedMemorySize, SMEM_FUSED);
    cudaFuncSetAttribute(gemmM_k<128, false>, cudaFuncAttributeMaxDynamicSharedMemorySize, SMEM128);

    // gat: 2 dsts per warp, 8 warps per block -> 16 dsts/block
    const int GAT_BLOCKS = (NN + 15) / 16;

    // launches 1-3 (keeps fused kernel in ncu capture slot 4)
    embed_k<<<(NN * 16 + 255) / 256, 256>>>(x, embed);   // also inits g_deg
    hist_k<<<(EE + 255) / 256, 256>>>(ei);
    blocksum_k<<<NBLK, 256>>>();

    // launch 4 = fused layer 0 (capture slot)
    fused_layer_k<<<GTB, 512, SMEM_FUSED>>>(h, lin_W, lin_b, gWl, gbl, gWr, gbr, xlh, xr);

    // finish CSR build (needed only by gat_k)
    bscan_k<<<1, 256>>>();
    scatter_scan_k<<<NBLK, 256>>>();
    fill_k<<<(EN + 255) / 256, 256>>>(ei);

    gat_k<<<GAT_BLOCKS, 256>>>(xlh, xr, gatt, gbias, h);

    for (int l = 1; l < 3; l++) {
        fused_layer_k<<<GTB, 512, SMEM_FUSED>>>(h, lin_W + l * 64 * 64, lin_b + l * 64,
                                                gWl + l * 64 * 128, gbl + l * 128,
                                                gWr + l * 64 * 128, gbr + l * 128, xlh, xr);
        gat_k<<<GAT_BLOCKS, 256>>>(xlh, xr, gatt + l * 128, gbias + l * 64, h);
    }

    gemmM_k<128, false><<<GTB, 256, SMEM128>>>(h, rW, rb, ro);
    zero_k<<<(GG * 128 / 4 + 255) / 256, 256>>>(out);
    segsum_k<<<(NN * 32 + 255) / 256, 256>>>(batch, ro, out);
}